// round 6
// baseline (speedup 1.0000x reference)
#include <cuda_runtime.h>
#include <cuda_bf16.h>

// out[i,j,:] = float(argmax(encoding_logits[clamp(qv[i,j],-128,127)+128, :]))
// (soft_codes - stop_gradient(soft_codes) == 0 exactly; gumbel_noise unused)

#define N_LEVELS 256
#define N_PIX (512 * 512)

__device__ float g_hard_table[N_LEVELS];

// Stage 1: one WARP per row (256 warps = 32 blocks x 8 warps). Lane l scans
// columns l, l+32, ..., l+224 (coalesced), then shuffle-reduce with
// first-index tiebreak (matching jnp.argmax).
__global__ void argmax_rows_kernel(const float* __restrict__ logits) {
    int warp = (blockIdx.x * blockDim.x + threadIdx.x) >> 5;   // row 0..255
    int lane = threadIdx.x & 31;
    const float* row = logits + warp * N_LEVELS;

    float best = -__FLT_MAX__;
    int bi = N_LEVELS;
#pragma unroll
    for (int j = 0; j < N_LEVELS / 32; ++j) {
        int k = lane + j * 32;
        float v = row[k];
        if (v > best || (v == best && k < bi)) { best = v; bi = k; }
    }
#pragma unroll
    for (int off = 16; off > 0; off >>= 1) {
        float ov = __shfl_down_sync(0xffffffffu, best, off);
        int oi = __shfl_down_sync(0xffffffffu, bi, off);
        if (ov > best || (ov == best && oi < bi)) { best = ov; bi = oi; }
    }
    if (lane == 0) g_hard_table[warp] = (float)bi;
}

// 256-bit evict-first store (sm_100+): 8 floats, 32B-aligned.
__device__ __forceinline__ void stg256_cs(float* p, float v) {
    asm volatile(
        "st.global.cs.v8.f32 [%0], {%1,%1,%1,%1,%1,%1,%1,%1};"
        :: "l"(p), "f"(v) : "memory");
}

// Stage 2 (PDL consumer): R4's winning geometry — block covers 32 pixels
// (128 KB contiguous), 8 threads per pixel — but with 4 x STG.256 per thread
// instead of 8 x STG.128 (half the LSU wavefronts, same bytes).
// Thread t -> pixel (t>>3), float8-chunks (t&7) + 8j, j=0..3.
// Per-warp store instruction = 8 x 32B = one full pixel 256B segment x 4 pixels.
__global__ void __launch_bounds__(256) broadcast_kernel(
    const int* __restrict__ qv, float* __restrict__ out) {
    int t = threadIdx.x;
    int pix = blockIdx.x * 32 + (t >> 3);
    int q = __ldg(qv + pix);                       // independent of stage 1
    q = min(max(q, -128), 127) + 128;
    float* p = out + (long long)pix * 256 + (t & 7) * 8;

#if __CUDA_ARCH__ >= 900
    cudaGridDependencySynchronize();               // wait for argmax results
#endif
    float v = g_hard_table[q];
#pragma unroll
    for (int j = 0; j < 4; ++j)
        stg256_cs(p + j * 64, v);
}

extern "C" void kernel_launch(void* const* d_in, const int* in_sizes, int n_in,
                              void* d_out, int out_size) {
    const int* qv = (const int*)d_in[0];           // [512,512] int32
    const float* logits = (const float*)d_in[1];   // [256,256] f32
    // d_in[2] (gumbel_noise) is mathematically unused.
    float* out = (float*)d_out;

    argmax_rows_kernel<<<32, 256>>>(logits);       // 256 warps, 1 per row

    // PDL: let broadcast_kernel launch early; it gates on stage 1 internally.
    cudaLaunchConfig_t cfg = {};
    cfg.gridDim = dim3(N_PIX / 32);                // 8192 blocks
    cfg.blockDim = dim3(256);
    cfg.stream = 0;
    cudaLaunchAttribute attr[1];
    attr[0].id = cudaLaunchAttributeProgrammaticStreamSerialization;
    attr[0].val.programmaticStreamSerializationAllowed = 1;
    cfg.attrs = attr;
    cfg.numAttrs = 1;
    cudaLaunchKernelEx(&cfg, broadcast_kernel, qv, out);
}